// round 4
// baseline (speedup 1.0000x reference)
#include <cuda_runtime.h>
#include <math.h>
#include <stdint.h>

// ---------------------------------------------------------------------------
// Problem dims (fixed)
// ---------------------------------------------------------------------------
constexpr int NL  = 6;
constexpr int NB  = 4;
constexpr int NT  = 1024;
constexpr int ND  = 1024;
constexpr int NH  = 16;
constexpr int NHD = 64;
constexpr int NDF = 4096;
constexpr int NM  = NB * NT;          // 4096 rows
constexpr float RMS_EPS = 1.1920929e-07f;
constexpr float LN_EPS  = 1e-5f;

// ---------------------------------------------------------------------------
// Scratch (no cudaMalloc allowed) — __device__ globals
// ---------------------------------------------------------------------------
__device__ float g_hattn[NM * ND];
__device__ float g_x    [NM * ND];
__device__ float g_qkv  [NM * 3 * ND];
__device__ float g_ctx  [NM * ND];
__device__ float g_vl   [NM * ND];
__device__ float g_hmlp [NM * ND];
__device__ float g_ffh  [NM * NDF];

// ---------------------------------------------------------------------------
// 1) full_attn_res: depth-softmax attention over the layer stack.
// ---------------------------------------------------------------------------
template <int LL>
__global__ void full_attn_res_kernel(const float* __restrict__ src,
                                     const float* __restrict__ extra,
                                     const float* __restrict__ proj,
                                     const float* __restrict__ rmsw,
                                     float* __restrict__ out) {
    __shared__ float sv[LL][ND];
    __shared__ float slog[8];
    __shared__ float red[64];

    const int row = blockIdx.x;                 // b*T + t
    const int tid = threadIdx.x;                // 256 threads
    const int lane = tid & 31, warp = tid >> 5;
    const long rowoff = (long)row * ND;
    const long layer_stride = (long)NB * NT * ND;

    #pragma unroll
    for (int l = 0; l < LL; ++l) {
        const float* p = (l < NL) ? (src + (long)l * layer_stride + rowoff)
                                  : (extra + rowoff);
        float ss = 0.f, pd = 0.f;
        for (int d = tid; d < ND; d += 256) {
            float x = p[d];
            sv[l][d] = x;
            ss += x * x;
            pd += proj[d] * rmsw[d] * x;
        }
        #pragma unroll
        for (int o = 16; o > 0; o >>= 1) {
            ss += __shfl_down_sync(0xffffffffu, ss, o);
            pd += __shfl_down_sync(0xffffffffu, pd, o);
        }
        if (lane == 0) { red[warp] = ss; red[32 + warp] = pd; }
        __syncthreads();
        if (warp == 0) {
            ss = (lane < 8) ? red[lane] : 0.f;
            pd = (lane < 8) ? red[32 + lane] : 0.f;
            #pragma unroll
            for (int o = 4; o > 0; o >>= 1) {
                ss += __shfl_down_sync(0xffffffffu, ss, o);
                pd += __shfl_down_sync(0xffffffffu, pd, o);
            }
            if (lane == 0)
                slog[l] = pd * rsqrtf(ss * (1.0f / ND) + RMS_EPS);
        }
        __syncthreads();
    }

    float mx = -1e30f;
    #pragma unroll
    for (int l = 0; l < LL; ++l) mx = fmaxf(mx, slog[l]);
    float w[LL], wsum = 0.f;
    #pragma unroll
    for (int l = 0; l < LL; ++l) { w[l] = expf(slog[l] - mx); wsum += w[l]; }
    const float inv = 1.f / wsum;

    for (int d = tid; d < ND; d += 256) {
        float acc = 0.f;
        #pragma unroll
        for (int l = 0; l < LL; ++l) acc += w[l] * sv[l][d];
        out[rowoff + d] = acc * inv;
    }
}

// ---------------------------------------------------------------------------
// 2) LayerNorm: one CTA per row.
// ---------------------------------------------------------------------------
__global__ void layernorm_kernel(const float* __restrict__ in,
                                 const float* __restrict__ w,
                                 const float* __restrict__ b,
                                 float* __restrict__ out) {
    __shared__ float sx[ND];
    __shared__ float red[64];
    __shared__ float smu, srstd;

    const int row = blockIdx.x;
    const int tid = threadIdx.x;
    const int lane = tid & 31, warp = tid >> 5;
    const float* p = in + (long)row * ND;

    float s = 0.f, s2 = 0.f;
    for (int d = tid; d < ND; d += 256) {
        float x = p[d];
        sx[d] = x;
        s += x; s2 += x * x;
    }
    #pragma unroll
    for (int o = 16; o > 0; o >>= 1) {
        s  += __shfl_down_sync(0xffffffffu, s, o);
        s2 += __shfl_down_sync(0xffffffffu, s2, o);
    }
    if (lane == 0) { red[warp] = s; red[32 + warp] = s2; }
    __syncthreads();
    if (warp == 0) {
        s  = (lane < 8) ? red[lane] : 0.f;
        s2 = (lane < 8) ? red[32 + lane] : 0.f;
        #pragma unroll
        for (int o = 4; o > 0; o >>= 1) {
            s  += __shfl_down_sync(0xffffffffu, s, o);
            s2 += __shfl_down_sync(0xffffffffu, s2, o);
        }
        if (lane == 0) {
            float mu = s * (1.0f / ND);
            float var = s2 * (1.0f / ND) - mu * mu;
            smu = mu;
            srstd = rsqrtf(var + LN_EPS);
        }
    }
    __syncthreads();
    const float mu = smu, rstd = srstd;
    float* po = out + (long)row * ND;
    for (int d = tid; d < ND; d += 256)
        po[d] = (sx[d] - mu) * rstd * w[d] + b[d];
}

// ---------------------------------------------------------------------------
// 3) 3xTF32 GEMM via mma.sync.m16n8k8: C[M,N] = A[M,K] @ W[N,K]^T + bias,
//    optional exact-GELU, optional residual add.
//    Split precision: x = hi + lo (both tf32); C += Ahi*Bhi + Ahi*Blo + Alo*Bhi
//    -> ~fp32 accuracy at 3x mma cost.
//    CTA 128x128, K-tile 8, 8 warps each computing 64x32 (4 m-frags x 4 n-frags).
//    hi/lo interleaved as float2 in smem -> one LDS.64 per fragment element.
//    Smem row stride 132 float2 (264 words == 8 mod 32) -> conflict-free
//    fragment loads in both half-warp phases.
// ---------------------------------------------------------------------------
__device__ __forceinline__ float gelu_exact(float x) {
    return 0.5f * x * (1.f + erff(x * 0.70710678118654752f));
}

__device__ __forceinline__ unsigned f2tf32(float x) {
    unsigned u;
    asm("cvt.rna.tf32.f32 %0, %1;" : "=r"(u) : "f"(x));
    return u;
}

__device__ __forceinline__ void mma_tf32(float* c, const unsigned* a,
                                         unsigned b0, unsigned b1) {
    asm volatile(
        "mma.sync.aligned.m16n8k8.row.col.f32.tf32.tf32.f32 "
        "{%0,%1,%2,%3}, {%4,%5,%6,%7}, {%8,%9}, {%0,%1,%2,%3};"
        : "+f"(c[0]), "+f"(c[1]), "+f"(c[2]), "+f"(c[3])
        : "r"(a[0]), "r"(a[1]), "r"(a[2]), "r"(a[3]), "r"(b0), "r"(b1));
}

constexpr int TBM = 128, TBN = 128, TBK = 8;
constexpr int TRS = 132;   // row stride in float2 units

__global__ __launch_bounds__(256)
void sgemm_tf32_kernel(const float* __restrict__ A, const float* __restrict__ Bw,
                       const float* __restrict__ bias, const float* __restrict__ add,
                       float* __restrict__ C, int Mdim, int Ndim, int Kdim, int act) {
    // interleaved (hi, lo) tiles, double buffered: [2][TBK][TRS] float2 each
    __shared__ float2 sA[2][TBK][TRS];
    __shared__ float2 sB[2][TBK][TRS];

    const int t    = threadIdx.x;
    const int lane = t & 31;
    const int w    = t >> 5;                // 0..7
    const int wm   = (w >> 2) * 64;         // 0 or 64
    const int wn   = (w & 3) * 32;          // 0,32,64,96
    const int l4   = lane & 3;
    const int l8   = lane >> 2;

    const int bm = blockIdx.y * TBM;
    const int bn = blockIdx.x * TBN;

    // loader: one float4 per matrix per thread per K-tile
    const int lm = t >> 1;                  // 0..127
    const int lk = (t & 1) * 4;             // 0 or 4

    float acc[4][4][4];
    #pragma unroll
    for (int f = 0; f < 4; ++f)
        #pragma unroll
        for (int g = 0; g < 4; ++g)
            #pragma unroll
            for (int i = 0; i < 4; ++i) acc[f][g][i] = 0.f;

    // ---- load first K-tile: gmem -> cvt hi/lo -> smem buffer 0 ----
    {
        float4 va = *(const float4*)&A [(long)(bm + lm) * Kdim + lk];
        float4 vb = *(const float4*)&Bw[(long)(bn + lm) * Kdim + lk];
        float ae[4] = {va.x, va.y, va.z, va.w};
        float be[4] = {vb.x, vb.y, vb.z, vb.w};
        #pragma unroll
        for (int e = 0; e < 4; ++e) {
            unsigned h = f2tf32(ae[e]);
            float hf = __uint_as_float(h);
            unsigned lo = f2tf32(ae[e] - hf);
            sA[0][lk + e][lm] = make_float2(hf, __uint_as_float(lo));
            h = f2tf32(be[e]);
            hf = __uint_as_float(h);
            lo = f2tf32(be[e] - hf);
            sB[0][lk + e][lm] = make_float2(hf, __uint_as_float(lo));
        }
    }
    __syncthreads();

    int cur = 0;
    for (int k0 = 0; k0 < Kdim; k0 += TBK) {
        const bool has_next = (k0 + TBK < Kdim);
        float4 va, vb;
        if (has_next) {
            va = *(const float4*)&A [(long)(bm + lm) * Kdim + k0 + TBK + lk];
            vb = *(const float4*)&Bw[(long)(bn + lm) * Kdim + k0 + TBK + lk];
        }

        // ---- fragment loads (hi,lo pairs via single LDS.64) ----
        unsigned ahi[4][4], alo[4][4];
        #pragma unroll
        for (int f = 0; f < 4; ++f) {
            const int col = wm + f * 16 + l8;
            float2 p0 = sA[cur][l4    ][col];
            float2 p1 = sA[cur][l4    ][col + 8];
            float2 p2 = sA[cur][l4 + 4][col];
            float2 p3 = sA[cur][l4 + 4][col + 8];
            ahi[f][0] = __float_as_uint(p0.x); alo[f][0] = __float_as_uint(p0.y);
            ahi[f][1] = __float_as_uint(p1.x); alo[f][1] = __float_as_uint(p1.y);
            ahi[f][2] = __float_as_uint(p2.x); alo[f][2] = __float_as_uint(p2.y);
            ahi[f][3] = __float_as_uint(p3.x); alo[f][3] = __float_as_uint(p3.y);
        }
        #pragma unroll
        for (int g = 0; g < 4; ++g) {
            const int coln = wn + g * 8 + l8;
            float2 q0 = sB[cur][l4    ][coln];
            float2 q1 = sB[cur][l4 + 4][coln];
            unsigned bh0 = __float_as_uint(q0.x), bl0 = __float_as_uint(q0.y);
            unsigned bh1 = __float_as_uint(q1.x), bl1 = __float_as_uint(q1.y);
            #pragma unroll
            for (int f = 0; f < 4; ++f) {
                mma_tf32(acc[f][g], ahi[f], bh0, bh1);   // hi*hi
                mma_tf32(acc[f][g], ahi[f], bl0, bl1);   // hi*lo
                mma_tf32(acc[f][g], alo[f], bh0, bh1);   // lo*hi
            }
        }

        if (has_next) {
            const int nxt = cur ^ 1;
            float ae[4] = {va.x, va.y, va.z, va.w};
            float be[4] = {vb.x, vb.y, vb.z, vb.w};
            #pragma unroll
            for (int e = 0; e < 4; ++e) {
                unsigned h = f2tf32(ae[e]);
                float hf = __uint_as_float(h);
                unsigned lo = f2tf32(ae[e] - hf);
                sA[nxt][lk + e][lm] = make_float2(hf, __uint_as_float(lo));
                h = f2tf32(be[e]);
                hf = __uint_as_float(h);
                lo = f2tf32(be[e] - hf);
                sB[nxt][lk + e][lm] = make_float2(hf, __uint_as_float(lo));
            }
            __syncthreads();
            cur = nxt;
        }
    }

    // ---- epilogue: bias (+gelu) (+residual) ----
    #pragma unroll
    for (int f = 0; f < 4; ++f) {
        const int r0 = bm + wm + f * 16 + l8;
        const int r1 = r0 + 8;
        #pragma unroll
        for (int g = 0; g < 4; ++g) {
            const int c = bn + wn + g * 8 + l4 * 2;
            float2 bi = *(const float2*)&bias[c];
            float v0 = acc[f][g][0] + bi.x;
            float v1 = acc[f][g][1] + bi.y;
            float v2 = acc[f][g][2] + bi.x;
            float v3 = acc[f][g][3] + bi.y;
            if (act == 1) {
                v0 = gelu_exact(v0); v1 = gelu_exact(v1);
                v2 = gelu_exact(v2); v3 = gelu_exact(v3);
            }
            if (add) {
                float2 a0 = *(const float2*)&add[(long)r0 * Ndim + c];
                float2 a1 = *(const float2*)&add[(long)r1 * Ndim + c];
                v0 += a0.x; v1 += a0.y; v2 += a1.x; v3 += a1.y;
            }
            *(float2*)&C[(long)r0 * Ndim + c] = make_float2(v0, v1);
            *(float2*)&C[(long)r1 * Ndim + c] = make_float2(v2, v3);
        }
    }
}

// ---------------------------------------------------------------------------
// 4) Causal flash attention, fp32. Grid (T/128, H, B), 128 threads.
// ---------------------------------------------------------------------------
__global__ __launch_bounds__(128, 3)
void flash_attn_kernel(const float* __restrict__ qkv, float* __restrict__ ctx) {
    __shared__ float Ks[32][64];
    __shared__ float Vs[32][64];
    __shared__ float Ss[128][33];

    const int b   = blockIdx.z;
    const int h   = blockIdx.y;
    const int tid = threadIdx.x;
    const int qg  = blockIdx.x * 128 + tid;

    const long qkv_row = (long)(b * NT + qg) * (3 * ND);
    const float* qrow = qkv + qkv_row + h * NHD;

    float q[64];
    #pragma unroll
    for (int i = 0; i < 16; ++i) {
        float4 v = *(const float4*)&qrow[i * 4];
        q[4 * i + 0] = v.x; q[4 * i + 1] = v.y;
        q[4 * i + 2] = v.z; q[4 * i + 3] = v.w;
    }

    float o[64];
    #pragma unroll
    for (int d = 0; d < 64; ++d) o[d] = 0.f;
    float m = -1e30f, lsum = 0.f;

    const int nkt = blockIdx.x * 4 + 4;
    for (int kt = 0; kt < nkt; ++kt) {
        const int kbase = kt * 32;
        __syncthreads();
        #pragma unroll
        for (int i = 0; i < 4; ++i) {
            int idx = tid + i * 128;
            int r = idx >> 4, c = (idx & 15) * 4;
            const long rb = (long)(b * NT + kbase + r) * (3 * ND) + h * NHD + c;
            *(float4*)&Ks[r][c] = *(const float4*)&qkv[rb + ND];
            *(float4*)&Vs[r][c] = *(const float4*)&qkv[rb + 2 * ND];
        }
        __syncthreads();

        float tmax = -1e30f;
        #pragma unroll 4
        for (int j = 0; j < 32; ++j) {
            float s = 0.f;
            #pragma unroll
            for (int i = 0; i < 16; ++i) {
                float4 kv = *(const float4*)&Ks[j][i * 4];
                s += q[4 * i + 0] * kv.x + q[4 * i + 1] * kv.y
                   + q[4 * i + 2] * kv.z + q[4 * i + 3] * kv.w;
            }
            s *= 0.125f;
            if (kbase + j > qg) s = -INFINITY;
            Ss[tid][j] = s;
            tmax = fmaxf(tmax, s);
        }
        const float mnew = fmaxf(m, tmax);
        const float corr = expf(m - mnew);
        m = mnew;
        lsum *= corr;
        #pragma unroll
        for (int d = 0; d < 64; ++d) o[d] *= corr;

        #pragma unroll 2
        for (int j = 0; j < 32; ++j) {
            float p = expf(Ss[tid][j] - m);
            lsum += p;
            #pragma unroll
            for (int i = 0; i < 16; ++i) {
                float4 vv = *(const float4*)&Vs[j][i * 4];
                o[4 * i + 0] += p * vv.x; o[4 * i + 1] += p * vv.y;
                o[4 * i + 2] += p * vv.z; o[4 * i + 3] += p * vv.w;
            }
        }
    }

    const float inv = 1.f / lsum;
    float* op = ctx + (long)(b * NT + qg) * ND + h * NHD;
    #pragma unroll
    for (int i = 0; i < 16; ++i) {
        float4 v;
        v.x = o[4 * i + 0] * inv; v.y = o[4 * i + 1] * inv;
        v.z = o[4 * i + 2] * inv; v.w = o[4 * i + 3] * inv;
        *(float4*)&op[i * 4] = v;
    }
}

// ---------------------------------------------------------------------------
// Orchestration
// ---------------------------------------------------------------------------
extern "C" void kernel_launch(void* const* d_in, const int* in_sizes, int n_in,
                              void* d_out, int out_size) {
    const float* sources    = (const float*)d_in[0];
    const float* w_attn     = (const float*)d_in[1];
    const float* rms_attn_w = (const float*)d_in[2];
    const float* w_ffn      = (const float*)d_in[3];
    const float* rms_ffn_w  = (const float*)d_in[4];
    const float* ln_attn_w  = (const float*)d_in[5];
    const float* ln_attn_b  = (const float*)d_in[6];
    const float* ln_ffn_w   = (const float*)d_in[7];
    const float* ln_ffn_b   = (const float*)d_in[8];
    const float* in_proj_w  = (const float*)d_in[9];
    const float* in_proj_b  = (const float*)d_in[10];
    const float* out_proj_w = (const float*)d_in[11];
    const float* out_proj_b = (const float*)d_in[12];
    const float* ffn_w1     = (const float*)d_in[13];
    const float* ffn_b1     = (const float*)d_in[14];
    const float* ffn_w2     = (const float*)d_in[15];
    const float* ffn_b2     = (const float*)d_in[16];
    float* out = (float*)d_out;

    float *hattn, *x, *qkv, *ctx, *vl, *hmlp, *ffh;
    cudaGetSymbolAddress((void**)&hattn, g_hattn);
    cudaGetSymbolAddress((void**)&x,     g_x);
    cudaGetSymbolAddress((void**)&qkv,   g_qkv);
    cudaGetSymbolAddress((void**)&ctx,   g_ctx);
    cudaGetSymbolAddress((void**)&vl,    g_vl);
    cudaGetSymbolAddress((void**)&hmlp,  g_hmlp);
    cudaGetSymbolAddress((void**)&ffh,   g_ffh);

    const float* v_prev = sources + (long)(NL - 1) * NB * NT * ND;

    // 1) h_attn = full_attn_res(sources)
    full_attn_res_kernel<NL><<<NM, 256>>>(sources, nullptr, w_attn, rms_attn_w, hattn);
    // 2) x = LN(h_attn)
    layernorm_kernel<<<NM, 256>>>(hattn, ln_attn_w, ln_attn_b, x);
    // 3) qkv = x @ in_proj_w^T + b
    sgemm_tf32_kernel<<<dim3(3 * ND / TBN, NM / TBM), 256>>>(
        x, in_proj_w, in_proj_b, nullptr, qkv, NM, 3 * ND, ND, 0);
    // 4) causal MHA
    flash_attn_kernel<<<dim3(NT / 128, NH, NB), 128>>>(qkv, ctx);
    // 5) v_l_attn = v_prev + ctx @ out_proj_w^T + b
    sgemm_tf32_kernel<<<dim3(ND / TBN, NM / TBM), 256>>>(
        ctx, out_proj_w, out_proj_b, v_prev, vl, NM, ND, ND, 0);
    // 6) h_mlp = full_attn_res([sources; v_l_attn])
    full_attn_res_kernel<NL + 1><<<NM, 256>>>(sources, vl, w_ffn, rms_ffn_w, hmlp);
    // 7) y = LN(h_mlp)  (reuse x)
    layernorm_kernel<<<NM, 256>>>(hmlp, ln_ffn_w, ln_ffn_b, x);
    // 8) ffh = gelu(y @ ffn_w1^T + b1)
    sgemm_tf32_kernel<<<dim3(NDF / TBN, NM / TBM), 256>>>(
        x, ffn_w1, ffn_b1, nullptr, ffh, NM, NDF, ND, 1);
    // 9) out = v_l_attn + ffh @ ffn_w2^T + b2
    sgemm_tf32_kernel<<<dim3(ND / TBN, NM / TBM), 256>>>(
        ffh, ffn_w2, ffn_b2, vl, out, NM, ND, NDF, 0);
}

// round 5
// speedup vs baseline: 2.5100x; 2.5100x over previous
#include <cuda_runtime.h>
#include <math.h>
#include <stdint.h>

// ---------------------------------------------------------------------------
// Problem dims (fixed)
// ---------------------------------------------------------------------------
constexpr int NL  = 6;
constexpr int NB  = 4;
constexpr int NT  = 1024;
constexpr int ND  = 1024;
constexpr int NH  = 16;
constexpr int NHD = 64;
constexpr int NDF = 4096;
constexpr int NM  = NB * NT;          // 4096 rows
constexpr float RMS_EPS = 1.1920929e-07f;
constexpr float LN_EPS  = 1e-5f;

// ---------------------------------------------------------------------------
// Scratch (no cudaMalloc allowed) — __device__ globals
// ---------------------------------------------------------------------------
__device__ float g_hattn[NM * ND];
__device__ float g_x    [NM * ND];
__device__ float g_qkv  [NM * 3 * ND];
__device__ float g_ctx  [NM * ND];
__device__ float g_vl   [NM * ND];
__device__ float g_hmlp [NM * ND];
__device__ float g_ffh  [NM * NDF];

// ---------------------------------------------------------------------------
// 1) full_attn_res: depth-softmax attention over the layer stack.
// ---------------------------------------------------------------------------
template <int LL>
__global__ void full_attn_res_kernel(const float* __restrict__ src,
                                     const float* __restrict__ extra,
                                     const float* __restrict__ proj,
                                     const float* __restrict__ rmsw,
                                     float* __restrict__ out) {
    __shared__ float sv[LL][ND];
    __shared__ float slog[8];
    __shared__ float red[64];

    const int row = blockIdx.x;                 // b*T + t
    const int tid = threadIdx.x;                // 256 threads
    const int lane = tid & 31, warp = tid >> 5;
    const long rowoff = (long)row * ND;
    const long layer_stride = (long)NB * NT * ND;

    #pragma unroll
    for (int l = 0; l < LL; ++l) {
        const float* p = (l < NL) ? (src + (long)l * layer_stride + rowoff)
                                  : (extra + rowoff);
        float ss = 0.f, pd = 0.f;
        for (int d = tid; d < ND; d += 256) {
            float x = p[d];
            sv[l][d] = x;
            ss += x * x;
            pd += proj[d] * rmsw[d] * x;
        }
        #pragma unroll
        for (int o = 16; o > 0; o >>= 1) {
            ss += __shfl_down_sync(0xffffffffu, ss, o);
            pd += __shfl_down_sync(0xffffffffu, pd, o);
        }
        if (lane == 0) { red[warp] = ss; red[32 + warp] = pd; }
        __syncthreads();
        if (warp == 0) {
            ss = (lane < 8) ? red[lane] : 0.f;
            pd = (lane < 8) ? red[32 + lane] : 0.f;
            #pragma unroll
            for (int o = 4; o > 0; o >>= 1) {
                ss += __shfl_down_sync(0xffffffffu, ss, o);
                pd += __shfl_down_sync(0xffffffffu, pd, o);
            }
            if (lane == 0)
                slog[l] = pd * rsqrtf(ss * (1.0f / ND) + RMS_EPS);
        }
        __syncthreads();
    }

    float mx = -1e30f;
    #pragma unroll
    for (int l = 0; l < LL; ++l) mx = fmaxf(mx, slog[l]);
    float w[LL], wsum = 0.f;
    #pragma unroll
    for (int l = 0; l < LL; ++l) { w[l] = expf(slog[l] - mx); wsum += w[l]; }
    const float inv = 1.f / wsum;

    for (int d = tid; d < ND; d += 256) {
        float acc = 0.f;
        #pragma unroll
        for (int l = 0; l < LL; ++l) acc += w[l] * sv[l][d];
        out[rowoff + d] = acc * inv;
    }
}

// ---------------------------------------------------------------------------
// 2) LayerNorm: one CTA per row.
// ---------------------------------------------------------------------------
__global__ void layernorm_kernel(const float* __restrict__ in,
                                 const float* __restrict__ w,
                                 const float* __restrict__ b,
                                 float* __restrict__ out) {
    __shared__ float sx[ND];
    __shared__ float red[64];
    __shared__ float smu, srstd;

    const int row = blockIdx.x;
    const int tid = threadIdx.x;
    const int lane = tid & 31, warp = tid >> 5;
    const float* p = in + (long)row * ND;

    float s = 0.f, s2 = 0.f;
    for (int d = tid; d < ND; d += 256) {
        float x = p[d];
        sx[d] = x;
        s += x; s2 += x * x;
    }
    #pragma unroll
    for (int o = 16; o > 0; o >>= 1) {
        s  += __shfl_down_sync(0xffffffffu, s, o);
        s2 += __shfl_down_sync(0xffffffffu, s2, o);
    }
    if (lane == 0) { red[warp] = s; red[32 + warp] = s2; }
    __syncthreads();
    if (warp == 0) {
        s  = (lane < 8) ? red[lane] : 0.f;
        s2 = (lane < 8) ? red[32 + lane] : 0.f;
        #pragma unroll
        for (int o = 4; o > 0; o >>= 1) {
            s  += __shfl_down_sync(0xffffffffu, s, o);
            s2 += __shfl_down_sync(0xffffffffu, s2, o);
        }
        if (lane == 0) {
            float mu = s * (1.0f / ND);
            float var = s2 * (1.0f / ND) - mu * mu;
            smu = mu;
            srstd = rsqrtf(var + LN_EPS);
        }
    }
    __syncthreads();
    const float mu = smu, rstd = srstd;
    float* po = out + (long)row * ND;
    for (int d = tid; d < ND; d += 256)
        po[d] = (sx[d] - mu) * rstd * w[d] + b[d];
}

// ---------------------------------------------------------------------------
// 3) TF32 GEMM via mma.sync.m16n8k8: C[M,N] = A[M,K] @ W[N,K]^T + bias,
//    optional exact-GELU, optional residual add.
//    Single-pass tf32 (inputs rounded to tf32, fp32 accumulate): dot-product
//    relative error ~1e-4, well under the 1e-3 gate.
//    CTA 128x128, K-tile 16, double-buffered smem (1 sync / K-tile).
//    smem layout [m][k] with row stride 20 floats:
//      frag LDS.32 banks = 20*l8 + l4 (+const) -> all 32 lanes distinct.
//    Loader: 4 aligned STS.128 per thread (no transpose, no conflicts).
//    8 warps, each 64x32 (4 m-frags x 4 n-frags).
// ---------------------------------------------------------------------------
__device__ __forceinline__ float gelu_exact(float x) {
    return 0.5f * x * (1.f + erff(x * 0.70710678118654752f));
}

__device__ __forceinline__ float f2tf32f(float x) {
    unsigned u;
    asm("cvt.rna.tf32.f32 %0, %1;" : "=r"(u) : "f"(x));
    return __uint_as_float(u);
}

__device__ __forceinline__ void mma_tf32(float* c, const unsigned* a,
                                         unsigned b0, unsigned b1) {
    asm volatile(
        "mma.sync.aligned.m16n8k8.row.col.f32.tf32.tf32.f32 "
        "{%0,%1,%2,%3}, {%4,%5,%6,%7}, {%8,%9}, {%0,%1,%2,%3};"
        : "+f"(c[0]), "+f"(c[1]), "+f"(c[2]), "+f"(c[3])
        : "r"(a[0]), "r"(a[1]), "r"(a[2]), "r"(a[3]), "r"(b0), "r"(b1));
}

constexpr int TBM = 128, TBN = 128, TBK = 16;
constexpr int TKS = 20;   // row stride in floats: 20 mod 32 banks -> frag-load conflict-free

__global__ __launch_bounds__(256, 2)
void sgemm_tf32_kernel(const float* __restrict__ A, const float* __restrict__ Bw,
                       const float* __restrict__ bias, const float* __restrict__ add,
                       float* __restrict__ C, int Mdim, int Ndim, int Kdim, int act) {
    __shared__ float sA[2][TBM][TKS];
    __shared__ float sB[2][TBN][TKS];

    const int t    = threadIdx.x;
    const int lane = t & 31;
    const int w    = t >> 5;                // 0..7
    const int wm   = (w >> 2) * 64;         // 0 or 64
    const int wn   = (w & 3) * 32;          // 0,32,64,96
    const int l4   = lane & 3;
    const int l8   = lane >> 2;

    const int bm = blockIdx.y * TBM;
    const int bn = blockIdx.x * TBN;

    // loader: slots t and t+256 of 512 float4 slots per matrix
    const int m0 = t >> 2;                  // 0..63
    const int kq = (t & 3) * 4;             // 0,4,8,12
    const int m1 = m0 + 64;                 // 64..127

    float acc[4][4][4];
    #pragma unroll
    for (int f = 0; f < 4; ++f)
        #pragma unroll
        for (int g = 0; g < 4; ++g)
            #pragma unroll
            for (int i = 0; i < 4; ++i) acc[f][g][i] = 0.f;

    // ---- first K-tile: gmem -> tf32 -> smem buffer 0 ----
    {
        float4 va0 = *(const float4*)&A [(long)(bm + m0) * Kdim + kq];
        float4 va1 = *(const float4*)&A [(long)(bm + m1) * Kdim + kq];
        float4 vb0 = *(const float4*)&Bw[(long)(bn + m0) * Kdim + kq];
        float4 vb1 = *(const float4*)&Bw[(long)(bn + m1) * Kdim + kq];
        float4 c0 = make_float4(f2tf32f(va0.x), f2tf32f(va0.y), f2tf32f(va0.z), f2tf32f(va0.w));
        float4 c1 = make_float4(f2tf32f(va1.x), f2tf32f(va1.y), f2tf32f(va1.z), f2tf32f(va1.w));
        float4 c2 = make_float4(f2tf32f(vb0.x), f2tf32f(vb0.y), f2tf32f(vb0.z), f2tf32f(vb0.w));
        float4 c3 = make_float4(f2tf32f(vb1.x), f2tf32f(vb1.y), f2tf32f(vb1.z), f2tf32f(vb1.w));
        *(float4*)&sA[0][m0][kq] = c0;
        *(float4*)&sA[0][m1][kq] = c1;
        *(float4*)&sB[0][m0][kq] = c2;
        *(float4*)&sB[0][m1][kq] = c3;
    }
    __syncthreads();

    int cur = 0;
    for (int k0 = 0; k0 < Kdim; k0 += TBK) {
        const bool has_next = (k0 + TBK < Kdim);
        float4 va0, va1, vb0, vb1;
        if (has_next) {
            const int kn = k0 + TBK + kq;
            va0 = *(const float4*)&A [(long)(bm + m0) * Kdim + kn];
            va1 = *(const float4*)&A [(long)(bm + m1) * Kdim + kn];
            vb0 = *(const float4*)&Bw[(long)(bn + m0) * Kdim + kn];
            vb1 = *(const float4*)&Bw[(long)(bn + m1) * Kdim + kn];
        }

        // ---- compute on buffer cur: two k8 slices ----
        #pragma unroll
        for (int ks = 0; ks < TBK; ks += 8) {
            unsigned a[4][4];
            #pragma unroll
            for (int f = 0; f < 4; ++f) {
                const int row = wm + f * 16 + l8;
                a[f][0] = __float_as_uint(sA[cur][row    ][ks + l4]);
                a[f][1] = __float_as_uint(sA[cur][row + 8][ks + l4]);
                a[f][2] = __float_as_uint(sA[cur][row    ][ks + l4 + 4]);
                a[f][3] = __float_as_uint(sA[cur][row + 8][ks + l4 + 4]);
            }
            #pragma unroll
            for (int g = 0; g < 4; ++g) {
                const int coln = wn + g * 8 + l8;
                unsigned b0 = __float_as_uint(sB[cur][coln][ks + l4]);
                unsigned b1 = __float_as_uint(sB[cur][coln][ks + l4 + 4]);
                #pragma unroll
                for (int f = 0; f < 4; ++f)
                    mma_tf32(acc[f][g], a[f], b0, b1);
            }
        }

        if (has_next) {
            const int nxt = cur ^ 1;
            float4 c0 = make_float4(f2tf32f(va0.x), f2tf32f(va0.y), f2tf32f(va0.z), f2tf32f(va0.w));
            float4 c1 = make_float4(f2tf32f(va1.x), f2tf32f(va1.y), f2tf32f(va1.z), f2tf32f(va1.w));
            float4 c2 = make_float4(f2tf32f(vb0.x), f2tf32f(vb0.y), f2tf32f(vb0.z), f2tf32f(vb0.w));
            float4 c3 = make_float4(f2tf32f(vb1.x), f2tf32f(vb1.y), f2tf32f(vb1.z), f2tf32f(vb1.w));
            *(float4*)&sA[nxt][m0][kq] = c0;
            *(float4*)&sA[nxt][m1][kq] = c1;
            *(float4*)&sB[nxt][m0][kq] = c2;
            *(float4*)&sB[nxt][m1][kq] = c3;
            __syncthreads();
            cur = nxt;
        }
    }

    // ---- epilogue: bias (+gelu) (+residual) ----
    #pragma unroll
    for (int f = 0; f < 4; ++f) {
        const int r0 = bm + wm + f * 16 + l8;
        const int r1 = r0 + 8;
        #pragma unroll
        for (int g = 0; g < 4; ++g) {
            const int c = bn + wn + g * 8 + l4 * 2;
            float2 bi = *(const float2*)&bias[c];
            float v0 = acc[f][g][0] + bi.x;
            float v1 = acc[f][g][1] + bi.y;
            float v2 = acc[f][g][2] + bi.x;
            float v3 = acc[f][g][3] + bi.y;
            if (act == 1) {
                v0 = gelu_exact(v0); v1 = gelu_exact(v1);
                v2 = gelu_exact(v2); v3 = gelu_exact(v3);
            }
            if (add) {
                float2 a0 = *(const float2*)&add[(long)r0 * Ndim + c];
                float2 a1 = *(const float2*)&add[(long)r1 * Ndim + c];
                v0 += a0.x; v1 += a0.y; v2 += a1.x; v3 += a1.y;
            }
            *(float2*)&C[(long)r0 * Ndim + c] = make_float2(v0, v1);
            *(float2*)&C[(long)r1 * Ndim + c] = make_float2(v2, v3);
        }
    }
}

// ---------------------------------------------------------------------------
// 4) Causal flash attention, fp32, fast exp. Grid (T/128, H, B), 128 threads.
// ---------------------------------------------------------------------------
__global__ __launch_bounds__(128, 3)
void flash_attn_kernel(const float* __restrict__ qkv, float* __restrict__ ctx) {
    __shared__ float Ks[32][64];
    __shared__ float Vs[32][64];
    __shared__ float Ss[128][33];

    const int b   = blockIdx.z;
    const int h   = blockIdx.y;
    const int tid = threadIdx.x;
    const int qg  = blockIdx.x * 128 + tid;

    const long qkv_row = (long)(b * NT + qg) * (3 * ND);
    const float* qrow = qkv + qkv_row + h * NHD;

    float q[64];
    #pragma unroll
    for (int i = 0; i < 16; ++i) {
        float4 v = *(const float4*)&qrow[i * 4];
        q[4 * i + 0] = v.x * 0.125f; q[4 * i + 1] = v.y * 0.125f;
        q[4 * i + 2] = v.z * 0.125f; q[4 * i + 3] = v.w * 0.125f;
    }

    float o[64];
    #pragma unroll
    for (int d = 0; d < 64; ++d) o[d] = 0.f;
    float m = -1e30f, lsum = 0.f;

    const int nkt = blockIdx.x * 4 + 4;
    for (int kt = 0; kt < nkt; ++kt) {
        const int kbase = kt * 32;
        __syncthreads();
        #pragma unroll
        for (int i = 0; i < 4; ++i) {
            int idx = tid + i * 128;
            int r = idx >> 4, c = (idx & 15) * 4;
            const long rb = (long)(b * NT + kbase + r) * (3 * ND) + h * NHD + c;
            *(float4*)&Ks[r][c] = *(const float4*)&qkv[rb + ND];
            *(float4*)&Vs[r][c] = *(const float4*)&qkv[rb + 2 * ND];
        }
        __syncthreads();

        float tmax = -1e30f;
        #pragma unroll 4
        for (int j = 0; j < 32; ++j) {
            float s = 0.f;
            #pragma unroll
            for (int i = 0; i < 16; ++i) {
                float4 kv = *(const float4*)&Ks[j][i * 4];
                s += q[4 * i + 0] * kv.x + q[4 * i + 1] * kv.y
                   + q[4 * i + 2] * kv.z + q[4 * i + 3] * kv.w;
            }
            if (kbase + j > qg) s = -INFINITY;
            Ss[tid][j] = s;
            tmax = fmaxf(tmax, s);
        }
        const float mnew = fmaxf(m, tmax);
        const float corr = __expf(m - mnew);
        m = mnew;
        lsum *= corr;
        #pragma unroll
        for (int d = 0; d < 64; ++d) o[d] *= corr;

        #pragma unroll 2
        for (int j = 0; j < 32; ++j) {
            float p = __expf(Ss[tid][j] - m);
            lsum += p;
            #pragma unroll
            for (int i = 0; i < 16; ++i) {
                float4 vv = *(const float4*)&Vs[j][i * 4];
                o[4 * i + 0] += p * vv.x; o[4 * i + 1] += p * vv.y;
                o[4 * i + 2] += p * vv.z; o[4 * i + 3] += p * vv.w;
            }
        }
    }

    const float inv = 1.f / lsum;
    float* op = ctx + (long)(b * NT + qg) * ND + h * NHD;
    #pragma unroll
    for (int i = 0; i < 16; ++i) {
        float4 v;
        v.x = o[4 * i + 0] * inv; v.y = o[4 * i + 1] * inv;
        v.z = o[4 * i + 2] * inv; v.w = o[4 * i + 3] * inv;
        *(float4*)&op[i * 4] = v;
    }
}

// ---------------------------------------------------------------------------
// Orchestration
// ---------------------------------------------------------------------------
extern "C" void kernel_launch(void* const* d_in, const int* in_sizes, int n_in,
                              void* d_out, int out_size) {
    const float* sources    = (const float*)d_in[0];
    const float* w_attn     = (const float*)d_in[1];
    const float* rms_attn_w = (const float*)d_in[2];
    const float* w_ffn      = (const float*)d_in[3];
    const float* rms_ffn_w  = (const float*)d_in[4];
    const float* ln_attn_w  = (const float*)d_in[5];
    const float* ln_attn_b  = (const float*)d_in[6];
    const float* ln_ffn_w   = (const float*)d_in[7];
    const float* ln_ffn_b   = (const float*)d_in[8];
    const float* in_proj_w  = (const float*)d_in[9];
    const float* in_proj_b  = (const float*)d_in[10];
    const float* out_proj_w = (const float*)d_in[11];
    const float* out_proj_b = (const float*)d_in[12];
    const float* ffn_w1     = (const float*)d_in[13];
    const float* ffn_b1     = (const float*)d_in[14];
    const float* ffn_w2     = (const float*)d_in[15];
    const float* ffn_b2     = (const float*)d_in[16];
    float* out = (float*)d_out;

    float *hattn, *x, *qkv, *ctx, *vl, *hmlp, *ffh;
    cudaGetSymbolAddress((void**)&hattn, g_hattn);
    cudaGetSymbolAddress((void**)&x,     g_x);
    cudaGetSymbolAddress((void**)&qkv,   g_qkv);
    cudaGetSymbolAddress((void**)&ctx,   g_ctx);
    cudaGetSymbolAddress((void**)&vl,    g_vl);
    cudaGetSymbolAddress((void**)&hmlp,  g_hmlp);
    cudaGetSymbolAddress((void**)&ffh,   g_ffh);

    const float* v_prev = sources + (long)(NL - 1) * NB * NT * ND;

    // 1) h_attn = full_attn_res(sources)
    full_attn_res_kernel<NL><<<NM, 256>>>(sources, nullptr, w_attn, rms_attn_w, hattn);
    // 2) x = LN(h_attn)
    layernorm_kernel<<<NM, 256>>>(hattn, ln_attn_w, ln_attn_b, x);
    // 3) qkv = x @ in_proj_w^T + b
    sgemm_tf32_kernel<<<dim3(3 * ND / TBN, NM / TBM), 256>>>(
        x, in_proj_w, in_proj_b, nullptr, qkv, NM, 3 * ND, ND, 0);
    // 4) causal MHA
    flash_attn_kernel<<<dim3(NT / 128, NH, NB), 128>>>(qkv, ctx);
    // 5) v_l_attn = v_prev + ctx @ out_proj_w^T + b
    sgemm_tf32_kernel<<<dim3(ND / TBN, NM / TBM), 256>>>(
        ctx, out_proj_w, out_proj_b, v_prev, vl, NM, ND, ND, 0);
    // 6) h_mlp = full_attn_res([sources; v_l_attn])
    full_attn_res_kernel<NL + 1><<<NM, 256>>>(sources, vl, w_ffn, rms_ffn_w, hmlp);
    // 7) y = LN(h_mlp)  (reuse x)
    layernorm_kernel<<<NM, 256>>>(hmlp, ln_ffn_w, ln_ffn_b, x);
    // 8) ffh = gelu(y @ ffn_w1^T + b1)
    sgemm_tf32_kernel<<<dim3(NDF / TBN, NM / TBM), 256>>>(
        x, ffn_w1, ffn_b1, nullptr, ffh, NM, NDF, ND, 1);
    // 9) out = v_l_attn + ffh @ ffn_w2^T + b2
    sgemm_tf32_kernel<<<dim3(ND / TBN, NM / TBM), 256>>>(
        ffh, ffn_w2, ffn_b2, vl, out, NM, ND, NDF, 0);
}